// round 1
// baseline (speedup 1.0000x reference)
#include <cuda_runtime.h>
#include <math.h>

// ---------------------------------------------------------------------------
// FCOS3D target assignment.
// Levels: strides (8,16,32,64,128), feat sizes (116x200, 58x100, 29x50, 15x25, 8x13)
// N points = 23200 + 5800 + 1450 + 375 + 104 = 30929
// Per (batch, point): argmin over M GT boxes of center-distance, gated by
// center-sampling radius and regress-range tests; then gather GT payload.
// Output (single float32 buffer, B*N*12 elements):
//   [0,       BN)  labels_3d
//   [BN,    10BN)  bbox_targets_3d (9 per point, row-major)
//   [10BN,  11BN)  centerness
//   [11BN,  12BN)  attr
// Within each section: level-major, then batch, then point-within-level
// (matches the reference's per-level concat of batch-major slices).
// ---------------------------------------------------------------------------

#define NLVL 5
#define NPTS 30929
#define INF_ 1.0e8f

__device__ __constant__ int   c_off[NLVL + 1] = {0, 23200, 29000, 30450, 30825, 30929};
__device__ __constant__ int   c_w[NLVL]       = {200, 100, 50, 25, 13};
__device__ __constant__ float c_s[NLVL]       = {8.f, 16.f, 32.f, 64.f, 128.f};
__device__ __constant__ float c_r0[NLVL]      = {-1.f, 48.f, 96.f, 192.f, 384.f};
__device__ __constant__ float c_r1[NLVL]      = {48.f, 96.f, 192.f, 384.f, 1.0e8f};

extern __shared__ __align__(16) char smem_raw[];

__global__ void fcos3d_target_kernel(
    const float* __restrict__ gt_bboxes,    // (B, M, 4)
    const float* __restrict__ g3d,          // (B, M, 9)
    const int*   __restrict__ gl3d,         // (B, M)
    const float* __restrict__ centers2d,    // (B, M, 2)
    const float* __restrict__ depths,       // (B, M)
    const int*   __restrict__ attrs,        // (B, M)
    float*       __restrict__ out,
    int M, int B)
{
    const int b = blockIdx.y;

    // Shared staging: bbox as float4, center as float2, payload 9 floats/GT:
    //   [depth, g3, g4, g5, yaw, g7, g8, label3d, attr]
    float4* s_bbox = reinterpret_cast<float4*>(smem_raw);
    float2* s_c    = reinterpret_cast<float2*>(s_bbox + M);
    float*  s_pay  = reinterpret_cast<float*>(s_c + M);

    for (int m = threadIdx.x; m < M; m += blockDim.x) {
        const float* bb = gt_bboxes + ((size_t)b * M + m) * 4;
        s_bbox[m] = make_float4(bb[0], bb[1], bb[2], bb[3]);
        const float* c = centers2d + ((size_t)b * M + m) * 2;
        s_c[m] = make_float2(c[0], c[1]);
        const float* g = g3d + ((size_t)b * M + m) * 9;
        float yaw = -atan2f(g[0], g[2]) + g[6];
        float* pp = s_pay + (size_t)m * 9;
        pp[0] = depths[b * M + m];
        pp[1] = g[3];
        pp[2] = g[4];
        pp[3] = g[5];
        pp[4] = yaw;
        pp[5] = g[7];
        pp[6] = g[8];
        pp[7] = (float)gl3d[b * M + m];
        pp[8] = (float)attrs[b * M + m];
    }
    __syncthreads();

    const int n = blockIdx.x * blockDim.x + threadIdx.x;
    if (n >= NPTS) return;

    // Level lookup (5-way).
    int lvl = 0;
#pragma unroll
    for (int i = 1; i < NLVL; i++)
        if (n >= c_off[i]) lvl = i;

    const int   p  = n - c_off[lvl];
    const int   w  = c_w[lvl];
    const float s  = c_s[lvl];
    const float x  = (float)(p % w) * s + 0.5f * s;
    const float y  = (float)(p / w) * s + 0.5f * s;
    const float r0 = c_r0[lvl];
    const float r1 = c_r1[lvl];
    const float rad = s * 1.5f;

    // Argmin over GTs (first-min tie-break like jnp.argmin: strict <).
    float best = 3.4e38f;
    int   bi   = 0;
#pragma unroll 4
    for (int m = 0; m < M; m++) {
        const float4 bb = s_bbox[m];
        const float2 c  = s_c[m];
        const float left   = x - bb.x;
        const float top    = y - bb.y;
        const float right  = bb.z - x;
        const float bottom = bb.w - y;
        const float mrd = fmaxf(fmaxf(left, top), fmaxf(right, bottom));
        const bool  in_rr = (mrd >= r0) && (mrd <= r1);
        const float cbx = fminf(x - (c.x - rad), c.x + rad - x);
        const float cby = fminf(y - (c.y - rad), c.y + rad - y);
        const bool  in_gt = fminf(cbx, cby) > 0.f;
        const float dx = x - c.x;
        const float dy = y - c.y;
        const float d  = (in_rr && in_gt) ? sqrtf(dx * dx + dy * dy) : INF_;
        if (d < best) { best = d; bi = m; }
    }

    const bool bg = (best >= INF_);

    // Gather the winner's payload (even for background, like the reference).
    const float2 c  = s_c[bi];
    const float  dx = x - c.x;
    const float  dy = y - c.y;
    const float* pp = s_pay + (size_t)bi * 9;

    // Centerness uses the un-normalized dx,dy.
    const float cent = expf(-2.5f * (sqrtf(dx * dx + dy * dy) / (1.414f * s * 1.5f)));

    // Output index: level-major, then batch, then point-within-level.
    const int BN   = B * NPTS;
    const int npl  = c_off[lvl + 1] - c_off[lvl];
    const int base = c_off[lvl] * B + b * npl + p;

    out[base] = bg ? 10.f : pp[7];                  // labels_3d (NUM_CLASSES=10 bg)

    float* bo = out + BN + (size_t)base * 9;        // bbox_targets_3d
    bo[0] = dx / s;
    bo[1] = dy / s;
    bo[2] = pp[0];
    bo[3] = pp[1];
    bo[4] = pp[2];
    bo[5] = pp[3];
    bo[6] = pp[4];
    bo[7] = pp[5];
    bo[8] = pp[6];

    out[10 * BN + base] = cent;                     // centerness
    out[11 * BN + base] = bg ? 9.f : pp[8];         // attr (NUM_ATTRS=9 bg)
}

extern "C" void kernel_launch(void* const* d_in, const int* in_sizes, int n_in,
                              void* d_out, int out_size)
{
    // Inputs (metadata order): gt_bboxes, gt_labels (unused), gt_bboxes_3d,
    // gt_labels_3d, centers2d, depths, attr_labels.
    const float* gt_bboxes = (const float*)d_in[0];
    const float* g3d       = (const float*)d_in[2];
    const int*   gl3d      = (const int*)  d_in[3];
    const float* centers2d = (const float*)d_in[4];
    const float* depths    = (const float*)d_in[5];
    const int*   attrs     = (const int*)  d_in[6];
    float* out = (float*)d_out;

    const int B = out_size / (12 * NPTS);
    const int M = in_sizes[1] / B;   // gt_labels has B*M elements

    const int threads = 256;
    dim3 grid((NPTS + threads - 1) / threads, B);
    size_t smem = (size_t)M * (sizeof(float4) + sizeof(float2) + 9 * sizeof(float));
    fcos3d_target_kernel<<<grid, threads, smem>>>(
        gt_bboxes, g3d, gl3d, centers2d, depths, attrs, out, M, B);
}

// round 2
// speedup vs baseline: 1.1358x; 1.1358x over previous
#include <cuda_runtime.h>
#include <math.h>

// ---------------------------------------------------------------------------
// FCOS3D target assignment — round 2.
// Changes vs R1: argmin on squared distance (no sqrt in loop), simplified
// center-sampling test (max(|dx|,|dy|) < r), reciprocal constants instead of
// divisions, and 2-way GT-loop split across lane pairs with shfl reduction
// (2x warp count -> better latency hiding on a residency-limited kernel).
// ---------------------------------------------------------------------------

#define NLVL 5
#define NPTS 30929
#define INF_ 1.0e8f

__device__ __constant__ int   c_off[NLVL + 1] = {0, 23200, 29000, 30450, 30825, 30929};
__device__ __constant__ int   c_w[NLVL]       = {200, 100, 50, 25, 13};
__device__ __constant__ float c_s[NLVL]       = {8.f, 16.f, 32.f, 64.f, 128.f};
__device__ __constant__ float c_inv_s[NLVL]   = {0.125f, 0.0625f, 0.03125f, 0.015625f, 0.0078125f};
// -2.5 / (1.414 * s * 1.5), precomputed (1-ULP vs reference's op sequence)
__device__ __constant__ float c_cent_k[NLVL]  = {
    -2.5f / (1.414f * 8.f   * 1.5f),
    -2.5f / (1.414f * 16.f  * 1.5f),
    -2.5f / (1.414f * 32.f  * 1.5f),
    -2.5f / (1.414f * 64.f  * 1.5f),
    -2.5f / (1.414f * 128.f * 1.5f)};
__device__ __constant__ float c_r0[NLVL]      = {-1.f, 48.f, 96.f, 192.f, 384.f};
__device__ __constant__ float c_r1[NLVL]      = {48.f, 96.f, 192.f, 384.f, 1.0e8f};

extern __shared__ __align__(16) char smem_raw[];

__global__ void fcos3d_target_kernel(
    const float* __restrict__ gt_bboxes,    // (B, M, 4)
    const float* __restrict__ g3d,          // (B, M, 9)
    const int*   __restrict__ gl3d,         // (B, M)
    const float* __restrict__ centers2d,    // (B, M, 2)
    const float* __restrict__ depths,       // (B, M)
    const int*   __restrict__ attrs,        // (B, M)
    float*       __restrict__ out,
    int M, int B)
{
    const int b = blockIdx.y;

    // Shared staging: bbox float4, center float2, payload 9 floats/GT:
    //   [depth, g3, g4, g5, yaw, g7, g8, label3d, attr]
    float4* s_bbox = reinterpret_cast<float4*>(smem_raw);
    float2* s_c    = reinterpret_cast<float2*>(s_bbox + M);
    float*  s_pay  = reinterpret_cast<float*>(s_c + M);

    for (int m = threadIdx.x; m < M; m += blockDim.x) {
        const float* bb = gt_bboxes + ((size_t)b * M + m) * 4;
        s_bbox[m] = make_float4(bb[0], bb[1], bb[2], bb[3]);
        const float* c = centers2d + ((size_t)b * M + m) * 2;
        s_c[m] = make_float2(c[0], c[1]);
        const float* g = g3d + ((size_t)b * M + m) * 9;
        float yaw = -atan2f(g[0], g[2]) + g[6];
        float* pp = s_pay + (size_t)m * 9;
        pp[0] = depths[b * M + m];
        pp[1] = g[3];
        pp[2] = g[4];
        pp[3] = g[5];
        pp[4] = yaw;
        pp[5] = g[7];
        pp[6] = g[8];
        pp[7] = (float)gl3d[b * M + m];
        pp[8] = (float)attrs[b * M + m];
    }
    __syncthreads();

    // Lane pairs share one point: even lane scans GT [0, M/2), odd [M/2, M).
    const int t    = blockIdx.x * blockDim.x + threadIdx.x;
    int       n    = t >> 1;
    const int half = t & 1;
    const bool valid = (n < NPTS);
    if (n >= NPTS) n = NPTS - 1;   // keep lanes convergent for the shuffle

    int lvl = 0;
#pragma unroll
    for (int i = 1; i < NLVL; i++)
        if (n >= c_off[i]) lvl = i;

    const int   p   = n - c_off[lvl];
    const int   w   = c_w[lvl];
    const float s   = c_s[lvl];
    const float x   = (float)(p % w) * s + 0.5f * s;
    const float y   = (float)(p / w) * s + 0.5f * s;
    const float r0  = c_r0[lvl];
    const float r1  = c_r1[lvl];
    const float rad = s * 1.5f;

    // Argmin over this lane's half of the GTs (squared distance; monotonic
    // under sqrt so ordering matches the reference).
    const int mh = M >> 1;
    const int m0 = half * mh;
    const int m1 = half ? M : mh;

    float best = 3.4e38f;
    int   bi   = m0;
#pragma unroll 8
    for (int m = m0; m < m1; m++) {
        const float4 bb = s_bbox[m];
        const float2 c  = s_c[m];
        const float dx = x - c.x;
        const float dy = y - c.y;
        const float left   = x - bb.x;
        const float top    = y - bb.y;
        const float right  = bb.z - x;
        const float bottom = bb.w - y;
        const float mrd = fmaxf(fmaxf(left, top), fmaxf(right, bottom));
        const bool  ok  = (mrd >= r0) & (mrd <= r1) &
                          (fmaxf(fabsf(dx), fabsf(dy)) < rad);
        const float d2 = ok ? fmaf(dx, dx, dy * dy) : INF_;
        if (d2 < best) { best = d2; bi = m; }
    }

    // Pair reduction (first-min tie-break: lower index wins on equality).
    const float o_best = __shfl_xor_sync(0xffffffffu, best, 1);
    const int   o_bi   = __shfl_xor_sync(0xffffffffu, bi, 1);
    if (o_best < best || (o_best == best && o_bi < bi)) { best = o_best; bi = o_bi; }

    if (!valid) return;

    const bool bg = (best >= INF_);

    const float2 c  = s_c[bi];
    const float  dx = x - c.x;
    const float  dy = y - c.y;
    const float* pp = s_pay + (size_t)bi * 9;

    const float cent = expf(c_cent_k[lvl] * sqrtf(fmaf(dx, dx, dy * dy)));

    const int BN   = B * NPTS;
    const int npl  = c_off[lvl + 1] - c_off[lvl];
    const int base = c_off[lvl] * B + b * npl + p;
    float* bo = out + BN + (size_t)base * 9;
    const float inv_s = c_inv_s[lvl];

    if (half == 0) {
        out[base]           = bg ? 10.f : pp[7];   // labels_3d
        out[10 * BN + base] = cent;                // centerness
        out[11 * BN + base] = bg ? 9.f : pp[8];    // attr
        bo[0] = dx * inv_s;
        bo[1] = dy * inv_s;
        bo[2] = pp[0];
    } else {
        bo[3] = pp[1];
        bo[4] = pp[2];
        bo[5] = pp[3];
        bo[6] = pp[4];
        bo[7] = pp[5];
        bo[8] = pp[6];
    }
}

extern "C" void kernel_launch(void* const* d_in, const int* in_sizes, int n_in,
                              void* d_out, int out_size)
{
    const float* gt_bboxes = (const float*)d_in[0];
    const float* g3d       = (const float*)d_in[2];
    const int*   gl3d      = (const int*)  d_in[3];
    const float* centers2d = (const float*)d_in[4];
    const float* depths    = (const float*)d_in[5];
    const int*   attrs     = (const int*)  d_in[6];
    float* out = (float*)d_out;

    const int B = out_size / (12 * NPTS);
    const int M = in_sizes[1] / B;

    const int threads = 256;
    dim3 grid((2 * NPTS + threads - 1) / threads, B);   // 2 lanes per point
    size_t smem = (size_t)M * (sizeof(float4) + sizeof(float2) + 9 * sizeof(float));
    fcos3d_target_kernel<<<grid, threads, smem>>>(
        gt_bboxes, g3d, gl3d, centers2d, depths, attrs, out, M, B);
}

// round 3
// speedup vs baseline: 1.5320x; 1.3488x over previous
#include <cuda_runtime.h>
#include <math.h>

// ---------------------------------------------------------------------------
// FCOS3D target assignment — round 3: spatial candidate pruning.
// A GT contributes a finite distance at (x,y) only if max(|x-cx|,|y-cy|) <
// 1.5*stride. Per block: compute the point bbox, filter the M GTs to those
// whose center lies in bbox +- rad_max (compacted in index order -> argmin
// tie-break preserved), then scan only the ~3-6 survivors per point.
// ---------------------------------------------------------------------------

#define NLVL 5
#define NPTS 30929
#define INF_ 1.0e8f

__device__ __constant__ int   c_off[NLVL + 1] = {0, 23200, 29000, 30450, 30825, 30929};
__device__ __constant__ int   c_w[NLVL]       = {200, 100, 50, 25, 13};
__device__ __constant__ float c_s[NLVL]       = {8.f, 16.f, 32.f, 64.f, 128.f};
__device__ __constant__ float c_inv_s[NLVL]   = {0.125f, 0.0625f, 0.03125f, 0.015625f, 0.0078125f};
__device__ __constant__ float c_cent_k[NLVL]  = {
    -2.5f / (1.414f * 8.f   * 1.5f),
    -2.5f / (1.414f * 16.f  * 1.5f),
    -2.5f / (1.414f * 32.f  * 1.5f),
    -2.5f / (1.414f * 64.f  * 1.5f),
    -2.5f / (1.414f * 128.f * 1.5f)};
__device__ __constant__ float c_r0[NLVL]      = {-1.f, 48.f, 96.f, 192.f, 384.f};
__device__ __constant__ float c_r1[NLVL]      = {48.f, 96.f, 192.f, 384.f, 1.0e8f};

extern __shared__ __align__(16) char smem_raw[];

__global__ void __launch_bounds__(128)
fcos3d_target_kernel(
    const float* __restrict__ gt_bboxes,    // (B, M, 4)
    const float* __restrict__ g3d,          // (B, M, 9)
    const int*   __restrict__ gl3d,         // (B, M)
    const float* __restrict__ centers2d,    // (B, M, 2)
    const float* __restrict__ depths,       // (B, M)
    const int*   __restrict__ attrs,        // (B, M)
    float*       __restrict__ out,
    int M, int B)
{
    const int b    = blockIdx.y;
    const int tid  = threadIdx.x;
    const int lane = tid & 31;
    const int wid  = tid >> 5;

    // Dynamic smem layout.
    float4* s_bbox = reinterpret_cast<float4*>(smem_raw);          // M
    float2* s_c    = reinterpret_cast<float2*>(s_bbox + M);        // M
    float*  s_pay  = reinterpret_cast<float*>(s_c + M);            // 9*M
    float4* s_cbb  = reinterpret_cast<float4*>(s_pay + 9 * M);     // M (compacted)
    float2* s_cc   = reinterpret_cast<float2*>(s_cbb + M);         // M
    int*    s_cidx = reinterpret_cast<int*>(s_cc + M);             // M

    __shared__ float s_red[4 * 5];
    __shared__ float s_box[5];     // bxmin, bxmax, bymin, bymax (expanded)
    __shared__ int   s_ncand;

    // ---- per-thread point coords (clamped for convergence) ----
    const int n_raw = blockIdx.x * blockDim.x + tid;
    const bool valid = (n_raw < NPTS);
    const int n = valid ? n_raw : (NPTS - 1);

    int lvl = 0;
#pragma unroll
    for (int i = 1; i < NLVL; i++)
        if (n >= c_off[i]) lvl = i;

    const int   p   = n - c_off[lvl];
    const int   w   = c_w[lvl];
    const float s   = c_s[lvl];
    const float x   = (float)(p % w) * s + 0.5f * s;
    const float y   = (float)(p / w) * s + 0.5f * s;
    const float r0  = c_r0[lvl];
    const float r1  = c_r1[lvl];
    const float rad = s * 1.5f;

    // ---- block bbox reduction (xmin,xmax,ymin,ymax,radmax) ----
    float xmn = x, xmx = x, ymn = y, ymx = y, rmx = rad;
#pragma unroll
    for (int o = 16; o > 0; o >>= 1) {
        xmn = fminf(xmn, __shfl_xor_sync(0xffffffffu, xmn, o));
        xmx = fmaxf(xmx, __shfl_xor_sync(0xffffffffu, xmx, o));
        ymn = fminf(ymn, __shfl_xor_sync(0xffffffffu, ymn, o));
        ymx = fmaxf(ymx, __shfl_xor_sync(0xffffffffu, ymx, o));
        rmx = fmaxf(rmx, __shfl_xor_sync(0xffffffffu, rmx, o));
    }
    if (lane == 0) {
        s_red[wid * 5 + 0] = xmn; s_red[wid * 5 + 1] = xmx;
        s_red[wid * 5 + 2] = ymn; s_red[wid * 5 + 3] = ymx;
        s_red[wid * 5 + 4] = rmx;
    }

    // ---- stage GT data (all threads) ----
    for (int m = tid; m < M; m += blockDim.x) {
        const float* bb = gt_bboxes + ((size_t)b * M + m) * 4;
        s_bbox[m] = make_float4(bb[0], bb[1], bb[2], bb[3]);
        const float* c = centers2d + ((size_t)b * M + m) * 2;
        s_c[m] = make_float2(c[0], c[1]);
        const float* g = g3d + ((size_t)b * M + m) * 9;
        float yaw = -atan2f(g[0], g[2]) + g[6];
        float* pp = s_pay + (size_t)m * 9;
        pp[0] = depths[b * M + m];
        pp[1] = g[3];
        pp[2] = g[4];
        pp[3] = g[5];
        pp[4] = yaw;
        pp[5] = g[7];
        pp[6] = g[8];
        pp[7] = (float)gl3d[b * M + m];
        pp[8] = (float)attrs[b * M + m];
    }
    __syncthreads();

    // ---- combine warp bboxes (thread 0) ----
    if (tid == 0) {
        float a0 = s_red[0], a1 = s_red[1], a2 = s_red[2], a3 = s_red[3], a4 = s_red[4];
#pragma unroll
        for (int k = 1; k < 4; k++) {
            a0 = fminf(a0, s_red[k * 5 + 0]);
            a1 = fmaxf(a1, s_red[k * 5 + 1]);
            a2 = fminf(a2, s_red[k * 5 + 2]);
            a3 = fmaxf(a3, s_red[k * 5 + 3]);
            a4 = fmaxf(a4, s_red[k * 5 + 4]);
        }
        s_box[0] = a0 - a4;   // bxmin
        s_box[1] = a1 + a4;   // bxmax
        s_box[2] = a2 - a4;   // bymin
        s_box[3] = a3 + a4;   // bymax
    }
    __syncthreads();

    // ---- filter + ordered compaction (warp 0) ----
    if (wid == 0) {
        const float bxmin = s_box[0], bxmax = s_box[1];
        const float bymin = s_box[2], bymax = s_box[3];
        int cnt = 0;
        for (int m0 = 0; m0 < M; m0 += 32) {
            const int m = m0 + lane;
            bool ok = false;
            if (m < M) {
                const float2 c = s_c[m];
                ok = (c.x >= bxmin) & (c.x <= bxmax) & (c.y >= bymin) & (c.y <= bymax);
            }
            const unsigned mask = __ballot_sync(0xffffffffu, ok);
            if (ok) {
                const int pos = cnt + __popc(mask & ((1u << lane) - 1u));
                s_cbb[pos]  = s_bbox[m];
                s_cc[pos]   = s_c[m];
                s_cidx[pos] = m;
            }
            cnt += __popc(mask);
        }
        if (lane == 0) s_ncand = cnt;
    }
    __syncthreads();

    const int ncand = s_ncand;

    // ---- argmin over candidates (squared distance; first-min tie-break) ----
    float best = INF_;
    int   bk   = -1;
    for (int k = 0; k < ncand; k++) {
        const float4 bb = s_cbb[k];
        const float2 c  = s_cc[k];
        const float dx = x - c.x;
        const float dy = y - c.y;
        const float left   = x - bb.x;
        const float top    = y - bb.y;
        const float right  = bb.z - x;
        const float bottom = bb.w - y;
        const float mrd = fmaxf(fmaxf(left, top), fmaxf(right, bottom));
        const bool ok = (mrd >= r0) & (mrd <= r1) &
                        (fmaxf(fabsf(dx), fabsf(dy)) < rad);
        const float d2 = ok ? fmaf(dx, dx, dy * dy) : INF_;
        if (d2 < best) { best = d2; bk = k; }
    }

    if (!valid) return;

    const bool bg = (best >= INF_);
    const int  bi = (bk >= 0) ? s_cidx[bk] : 0;   // all-INF argmin -> index 0

    const float2 c  = s_c[bi];
    const float  dx = x - c.x;
    const float  dy = y - c.y;
    const float* pp = s_pay + (size_t)bi * 9;

    const float cent = expf(c_cent_k[lvl] * sqrtf(fmaf(dx, dx, dy * dy)));

    const int BN   = B * NPTS;
    const int npl  = c_off[lvl + 1] - c_off[lvl];
    const int base = c_off[lvl] * B + b * npl + p;
    const float inv_s = c_inv_s[lvl];

    out[base]           = bg ? 10.f : pp[7];   // labels_3d
    out[10 * BN + base] = cent;                // centerness
    out[11 * BN + base] = bg ? 9.f : pp[8];    // attr

    float* bo = out + BN + (size_t)base * 9;   // bbox_targets_3d
    bo[0] = dx * inv_s;
    bo[1] = dy * inv_s;
    bo[2] = pp[0];
    bo[3] = pp[1];
    bo[4] = pp[2];
    bo[5] = pp[3];
    bo[6] = pp[4];
    bo[7] = pp[5];
    bo[8] = pp[6];
}

extern "C" void kernel_launch(void* const* d_in, const int* in_sizes, int n_in,
                              void* d_out, int out_size)
{
    const float* gt_bboxes = (const float*)d_in[0];
    const float* g3d       = (const float*)d_in[2];
    const int*   gl3d      = (const int*)  d_in[3];
    const float* centers2d = (const float*)d_in[4];
    const float* depths    = (const float*)d_in[5];
    const int*   attrs     = (const int*)  d_in[6];
    float* out = (float*)d_out;

    const int B = out_size / (12 * NPTS);
    const int M = in_sizes[1] / B;

    const int threads = 128;
    dim3 grid((NPTS + threads - 1) / threads, B);
    // bbox(16M) + c(8M) + pay(36M) + cbb(16M) + cc(8M) + cidx(4M)
    size_t smem = (size_t)M * (16 + 8 + 36 + 16 + 8 + 4);
    fcos3d_target_kernel<<<grid, threads, smem>>>(
        gt_bboxes, g3d, gl3d, centers2d, depths, attrs, out, M, B);
}